// round 1
// baseline (speedup 1.0000x reference)
#include <cuda_runtime.h>

#define DIM 3072
#define HEADS 24
#define HD 128
#define BB 2
#define S_IMG 1024
#define S_TXT 512
#define SS 1536
#define SCALE_QK 0.08838834764831843f  // 1/sqrt(128)

// ---------------- scratch (device globals; no allocation allowed) ----------
__device__ float g_Qb[BB * SS * DIM];
__device__ float g_Kb[BB * SS * DIM];
__device__ float g_Vb[BB * SS * DIM];
__device__ float g_AO[BB * SS * DIM];

// ---------------------------------------------------------------------------
// Generic fp32 GEMM: C[mrow(m), n] = sum_k A[arow(m), k] * W[k, n] + bias[n]
// arow(m) = (m/aSeg)*aJoint + aOff + m%aSeg   (identity if aSeg >= M, aOff=0)
// crow(m) analogous. K = N = DIM = 3072 fixed. M = gridDim.y*128.
// Tile 128x128x8, 256 threads, 8x8 per-thread microtile.
// ---------------------------------------------------------------------------
__global__ __launch_bounds__(256) void gemm_k(
    const float* __restrict__ A, const float* __restrict__ W,
    const float* __restrict__ bias, float* __restrict__ C,
    int aSeg, int aOff, int aJoint,
    int cSeg, int cOff, int cJoint)
{
    __shared__ float As[8][128];
    __shared__ float Bs[8][128];

    const int tid = threadIdx.x;
    const int tx = tid & 15;        // 0..15 -> 8 cols each
    const int ty = tid >> 4;        // 0..15 -> 8 rows each
    const int m0 = blockIdx.y << 7;
    const int n0 = blockIdx.x << 7;

    float acc[8][8];
#pragma unroll
    for (int i = 0; i < 8; i++)
#pragma unroll
        for (int j = 0; j < 8; j++) acc[i][j] = 0.f;

    // A tile load: 128 rows x 8 k  -> 256 float4 (one per thread), transposed store
    const int aRowL = tid >> 1;
    const int aColL = (tid & 1) << 2;
    // W tile load: 8 k x 128 n -> 256 float4 (one per thread)
    const int bRowL = tid >> 5;
    const int bColL = (tid & 31) << 2;

    const int mA = m0 + aRowL;
    const long arow = (long)(mA / aSeg) * aJoint + aOff + (mA % aSeg);
    const float* Aptr = A + arow * (long)DIM + aColL;
    const float* Wptr = W + (long)bRowL * DIM + n0 + bColL;

    for (int k0 = 0; k0 < DIM; k0 += 8) {
        float4 av = *(const float4*)(Aptr + k0);
        float4 bv = *(const float4*)(Wptr + (long)k0 * DIM);
        As[aColL + 0][aRowL] = av.x;
        As[aColL + 1][aRowL] = av.y;
        As[aColL + 2][aRowL] = av.z;
        As[aColL + 3][aRowL] = av.w;
        *(float4*)&Bs[bRowL][bColL] = bv;
        __syncthreads();

#pragma unroll
        for (int kk = 0; kk < 8; kk++) {
            float ra[8], rb[8];
#pragma unroll
            for (int i = 0; i < 8; i++) ra[i] = As[kk][ty * 8 + i];
#pragma unroll
            for (int j = 0; j < 8; j++) rb[j] = Bs[kk][tx * 8 + j];
#pragma unroll
            for (int i = 0; i < 8; i++)
#pragma unroll
                for (int j = 0; j < 8; j++) acc[i][j] += ra[i] * rb[j];
        }
        __syncthreads();
    }

#pragma unroll
    for (int i = 0; i < 8; i++) {
        const int m = m0 + ty * 8 + i;
        const long crow = (long)(m / cSeg) * cJoint + cOff + (m % cSeg);
        float* cp = C + crow * (long)DIM + n0 + tx * 8;
        const float* bp = bias + n0 + tx * 8;
#pragma unroll
        for (int j = 0; j < 8; j++) cp[j] = acc[i][j] + bp[j];
    }
}

// ---------------------------------------------------------------------------
// Fused per-head RMSNorm (+gain, source-dependent) + RoPE for Q and K.
// grid.x = B*S*HEADS, grid.y = 0 -> Q, 1 -> K. 128 threads = one head row.
// ---------------------------------------------------------------------------
__global__ __launch_bounds__(128) void rmsrope_k(
    float* __restrict__ Q, float* __restrict__ K,
    const float* __restrict__ cosb, const float* __restrict__ sinb,
    const float* __restrict__ gq, const float* __restrict__ gk,
    const float* __restrict__ gqc, const float* __restrict__ gkc)
{
    const int idx = blockIdx.x;
    const int h = idx % HEADS;
    const int s = (idx / HEADS) % SS;
    const int b = idx / (HEADS * SS);

    float* buf = (blockIdx.y == 0 ? Q : K) + ((long)(b * SS + s)) * DIM + h * HD;
    const float* g = (blockIdx.y == 0) ? (s < S_TXT ? gqc : gq)
                                       : (s < S_TXT ? gkc : gk);
    const int d = threadIdx.x;
    float v = buf[d];

    float sq = v * v;
#pragma unroll
    for (int off = 16; off; off >>= 1) sq += __shfl_xor_sync(0xffffffffu, sq, off);
    __shared__ float red[4];
    if ((d & 31) == 0) red[d >> 5] = sq;
    __syncthreads();
    const float tot = red[0] + red[1] + red[2] + red[3];
    const float inv = rsqrtf(tot * (1.0f / HD) + 1e-6f);

    __shared__ float sm[HD];
    sm[d] = v * inv * g[d];
    __syncthreads();

    const int i = d >> 1;
    const float c = cosb[s * (HD / 2) + i];
    const float sn = sinb[s * (HD / 2) + i];
    const float x1 = sm[2 * i];
    const float x2 = sm[2 * i + 1];
    buf[d] = (d & 1) ? (x1 * sn + x2 * c) : (x1 * c - x2 * sn);
}

// ---------------------------------------------------------------------------
// Flash attention, fp32 online softmax. Block = 128 threads, 32 q-rows.
// Thread t: row r = t&31, col-group g = t>>5 (owns O cols g*32..g*32+31,
// S cols g*8..g*8+7). KV chunks of 32 rows; K buffer reused for V.
// grid = (SS/32, B*HEADS)
// ---------------------------------------------------------------------------
__global__ __launch_bounds__(128) void attn_k(
    const float* __restrict__ Q, const float* __restrict__ K,
    const float* __restrict__ V, float* __restrict__ O)
{
    __shared__ float Qs[32][129];
    __shared__ float KVs[32][129];
    __shared__ float Ss[32][33];
    __shared__ float redm[4][32];
    __shared__ float redl[4][32];

    const int q0 = blockIdx.x * 32;
    const int bh = blockIdx.y;
    const int b = bh / HEADS;
    const int h = bh % HEADS;
    const long bofs = (long)b * SS * DIM + h * HD;

    const int t = threadIdx.x;
    const int r = t & 31;
    const int g = t >> 5;
    const int c0 = g * 8;
    const int d0 = g * 32;

    for (int idx = t; idx < 32 * HD; idx += 128) {
        const int rr = idx >> 7, d = idx & 127;
        Qs[rr][d] = Q[bofs + (long)(q0 + rr) * DIM + d] * SCALE_QK;
    }

    float m = -1e30f, l = 0.f;
    float o[32];
#pragma unroll
    for (int i = 0; i < 32; i++) o[i] = 0.f;
    __syncthreads();

    for (int kv0 = 0; kv0 < SS; kv0 += 32) {
        // load K chunk
        for (int idx = t; idx < 32 * HD; idx += 128) {
            const int rr = idx >> 7, d = idx & 127;
            KVs[rr][d] = K[bofs + (long)(kv0 + rr) * DIM + d];
        }
        __syncthreads();

        // S = Q K^T for this thread's 8 columns
        float sv[8];
#pragma unroll
        for (int j = 0; j < 8; j++) sv[j] = 0.f;
        for (int d = 0; d < HD; d++) {
            const float qv = Qs[r][d];
#pragma unroll
            for (int j = 0; j < 8; j++) sv[j] += qv * KVs[c0 + j][d];
        }
        float pmax = sv[0];
#pragma unroll
        for (int j = 1; j < 8; j++) pmax = fmaxf(pmax, sv[j]);
        redm[g][r] = pmax;
        __syncthreads();  // K reads done; row partial-max available

        const float mch = fmaxf(fmaxf(redm[0][r], redm[1][r]),
                                fmaxf(redm[2][r], redm[3][r]));
        const float mnew = fmaxf(m, mch);
        const float alpha = __expf(m - mnew);
        float psum = 0.f;
#pragma unroll
        for (int j = 0; j < 8; j++) {
            const float p = __expf(sv[j] - mnew);
            Ss[r][c0 + j] = p;
            psum += p;
        }
        redl[g][r] = psum;

        // load V chunk into same buffer (K consumed)
        for (int idx = t; idx < 32 * HD; idx += 128) {
            const int rr = idx >> 7, d = idx & 127;
            KVs[rr][d] = V[bofs + (long)(kv0 + rr) * DIM + d];
        }
        __syncthreads();

        l = l * alpha + redl[0][r] + redl[1][r] + redl[2][r] + redl[3][r];
        m = mnew;
#pragma unroll
        for (int i = 0; i < 32; i++) o[i] *= alpha;
        for (int c = 0; c < 32; c++) {
            const float p = Ss[r][c];
#pragma unroll
            for (int i = 0; i < 32; i++) o[i] += p * KVs[c][d0 + i];
        }
        __syncthreads();  // protect KVs before next chunk's K load
    }

    const float invl = 1.0f / l;
    float* op = O + bofs + (long)(q0 + r) * DIM + d0;
#pragma unroll
    for (int i = 0; i < 32; i++) op[i] = o[i] * invl;
}

// ---------------------------------------------------------------------------
extern "C" void kernel_launch(void* const* d_in, const int* in_sizes, int n_in,
                              void* d_out, int out_size)
{
    const float* x    = (const float*)d_in[0];
    const float* ctx  = (const float*)d_in[1];
    const float* cosb = (const float*)d_in[2];
    const float* sinb = (const float*)d_in[3];
    const float* wq   = (const float*)d_in[4];
    const float* bq   = (const float*)d_in[5];
    const float* wk   = (const float*)d_in[6];
    const float* bk   = (const float*)d_in[7];
    const float* wv   = (const float*)d_in[8];
    const float* bv   = (const float*)d_in[9];
    const float* wqc  = (const float*)d_in[10];
    const float* bqc  = (const float*)d_in[11];
    const float* wkc  = (const float*)d_in[12];
    const float* bkc  = (const float*)d_in[13];
    const float* wvc  = (const float*)d_in[14];
    const float* bvc  = (const float*)d_in[15];
    const float* w_out     = (const float*)d_in[16];
    const float* b_out     = (const float*)d_in[17];
    const float* w_add_out = (const float*)d_in[18];
    const float* b_add_out = (const float*)d_in[19];
    const float* gq  = (const float*)d_in[20];
    const float* gk  = (const float*)d_in[21];
    const float* gqc = (const float*)d_in[22];
    const float* gkc = (const float*)d_in[23];

    float* out = (float*)d_out;

    float *Q, *K, *V, *AO;
    cudaGetSymbolAddress((void**)&Q, g_Qb);
    cudaGetSymbolAddress((void**)&K, g_Kb);
    cudaGetSymbolAddress((void**)&V, g_Vb);
    cudaGetSymbolAddress((void**)&AO, g_AO);

    const dim3 gridTxt(DIM / 128, (BB * S_TXT) / 128);   // 24 x 8
    const dim3 gridImg(DIM / 128, (BB * S_IMG) / 128);   // 24 x 16

    // --- QKV projections into joint [B, SS, DIM] buffers ---
    // txt rows: ctx (contiguous A), C rows -> (b*1536 + s)
    gemm_k<<<gridTxt, 256>>>(ctx, wqc, bqc, Q, BB * S_TXT, 0, BB * S_TXT,
                             S_TXT, 0, SS);
    gemm_k<<<gridTxt, 256>>>(ctx, wkc, bkc, K, BB * S_TXT, 0, BB * S_TXT,
                             S_TXT, 0, SS);
    gemm_k<<<gridTxt, 256>>>(ctx, wvc, bvc, V, BB * S_TXT, 0, BB * S_TXT,
                             S_TXT, 0, SS);
    // img rows: x (contiguous A), C rows -> (b*1536 + 512 + s)
    gemm_k<<<gridImg, 256>>>(x, wq, bq, Q, BB * S_IMG, 0, BB * S_IMG,
                             S_IMG, S_TXT, SS);
    gemm_k<<<gridImg, 256>>>(x, wk, bk, K, BB * S_IMG, 0, BB * S_IMG,
                             S_IMG, S_TXT, SS);
    gemm_k<<<gridImg, 256>>>(x, wv, bv, V, BB * S_IMG, 0, BB * S_IMG,
                             S_IMG, S_TXT, SS);

    // --- RMSNorm + RoPE on Q and K ---
    rmsrope_k<<<dim3(BB * SS * HEADS, 2), 128>>>(Q, K, cosb, sinb,
                                                 gq, gk, gqc, gkc);

    // --- attention ---
    attn_k<<<dim3(SS / 32, BB * HEADS), 128>>>(Q, K, V, AO);

    // --- output projections: d_out = [txt(2,512,3072) | img(2,1024,3072)] ---
    gemm_k<<<gridTxt, 256>>>(AO, w_add_out, b_add_out, out,
                             S_TXT, 0, SS,               // A rows from joint txt slice
                             BB * S_TXT, 0, BB * S_TXT); // C contiguous
    gemm_k<<<gridImg, 256>>>(AO, w_out, b_out, out + (long)BB * S_TXT * DIM,
                             S_IMG, S_TXT, SS,
                             BB * S_IMG, 0, BB * S_IMG);
}

// round 3
// speedup vs baseline: 1.5540x; 1.5540x over previous
#include <cuda_runtime.h>
#include <cuda_bf16.h>
#include <cstdint>

#define DIM 3072
#define HEADS 24
#define HD 128
#define BB 2
#define S_IMG 1024
#define S_TXT 512
#define SS 1536
#define SCALE_QK 0.08838834764831843f  // 1/sqrt(128)

#define KBIG (3 * DIM)    // 9216 : split-K [hi*hi + hi*lo + lo*hi]
#define BM 128
#define BN 128
#define BK 32
#define NIT (KBIG / BK)   // 288
#define PAD 40            // bf16 row stride (80B): conflict-free ldmatrix

// ---------------- scratch (device globals; no allocation allowed) ----------
__device__ float g_Qb[BB * SS * DIM];
__device__ float g_Kb[BB * SS * DIM];
__device__ float g_Vb[BB * SS * DIM];
__device__ float g_AO[BB * SS * DIM];
__device__ __nv_bfloat16 g_Wt[8ll * DIM * KBIG];      // 8 transposed split weights
__device__ __nv_bfloat16 g_Ab[(long)BB * SS * KBIG];  // split activations (reused)

// ------------------------------- PTX helpers -------------------------------
__device__ __forceinline__ uint32_t smem_u32(const void* p) {
    uint32_t a;
    asm("{ .reg .u64 t; cvta.to.shared.u64 t, %1; cvt.u32.u64 %0, t; }"
        : "=r"(a) : "l"(p));
    return a;
}
#define CP_ASYNC16(dst, src) \
    asm volatile("cp.async.cg.shared.global [%0], [%1], 16;" :: "r"(dst), "l"(src) : "memory")
#define CP_COMMIT() asm volatile("cp.async.commit_group;" ::: "memory")
#define CP_WAIT1() asm volatile("cp.async.wait_group 1;" ::: "memory")
#define CP_WAIT0() asm volatile("cp.async.wait_group 0;" ::: "memory")

__device__ __forceinline__ void ldsm4(uint32_t& r0, uint32_t& r1, uint32_t& r2,
                                      uint32_t& r3, uint32_t addr) {
    asm volatile("ldmatrix.sync.aligned.m8n8.x4.shared.b16 {%0,%1,%2,%3}, [%4];"
                 : "=r"(r0), "=r"(r1), "=r"(r2), "=r"(r3) : "r"(addr));
}
__device__ __forceinline__ void mma16816(float* d, uint32_t a0, uint32_t a1,
                                         uint32_t a2, uint32_t a3,
                                         uint32_t b0, uint32_t b1) {
    asm volatile("mma.sync.aligned.m16n8k16.row.col.f32.bf16.bf16.f32 "
                 "{%0,%1,%2,%3}, {%4,%5,%6,%7}, {%8,%9}, {%0,%1,%2,%3};"
                 : "+f"(d[0]), "+f"(d[1]), "+f"(d[2]), "+f"(d[3])
                 : "r"(a0), "r"(a1), "r"(a2), "r"(a3), "r"(b0), "r"(b1));
}

// ---------------------------------------------------------------------------
// Weight transpose + bf16 split: W[k][n] fp32 -> Wt[n][0:D]=hi, [D:2D]=lo, [2D:3D]=hi
// ---------------------------------------------------------------------------
__global__ __launch_bounds__(256) void wsplit_k(const float* __restrict__ W,
                                                __nv_bfloat16* __restrict__ Wt) {
    __shared__ float t[32][33];
    const int k0 = blockIdx.x * 32, n0 = blockIdx.y * 32;
    const int tx = threadIdx.x, ty = threadIdx.y;
#pragma unroll
    for (int r = ty; r < 32; r += 8)
        t[r][tx] = W[(long)(k0 + r) * DIM + n0 + tx];
    __syncthreads();
#pragma unroll
    for (int r = ty; r < 32; r += 8) {
        float v = t[tx][r];  // = W[k0+tx][n0+r]
        __nv_bfloat16 hi = __float2bfloat16(v);
        __nv_bfloat16 lo = __float2bfloat16(v - __bfloat162float(hi));
        long ro = (long)(n0 + r) * KBIG + k0 + tx;
        Wt[ro] = hi;
        Wt[ro + DIM] = lo;
        Wt[ro + 2 * DIM] = hi;
    }
}

// Activation split: A[m][k] fp32 -> Ab[m][0:D]=hi, [D:2D]=hi, [2D:3D]=lo
__global__ __launch_bounds__(256) void asplit_k(const float* __restrict__ A,
                                                __nv_bfloat16* __restrict__ Ab, int n) {
    int i = blockIdx.x * 256 + threadIdx.x;
    if (i >= n) return;
    int m = i / DIM, c = i - m * DIM;
    float v = A[i];
    __nv_bfloat16 hi = __float2bfloat16(v);
    __nv_bfloat16 lo = __float2bfloat16(v - __bfloat162float(hi));
    long ro = (long)m * KBIG + c;
    Ab[ro] = hi;
    Ab[ro + DIM] = hi;
    Ab[ro + 2 * DIM] = lo;
}

// ---------------------------------------------------------------------------
// Warp-MMA bf16 GEMM: C[crow(m)][n] = sum_k A[arow(m)][k]*Wt[n][k] + bias[n]
// 128x128x32 tiles, 8 warps (2m x 4n), warp tile 64x32, HMMA m16n8k16,
// cp.async double buffer, padded-40 smem (conflict-free ldmatrix).
// ---------------------------------------------------------------------------
__global__ __launch_bounds__(256, 1) void gemm_mma(
    const __nv_bfloat16* __restrict__ A, const __nv_bfloat16* __restrict__ Bw,
    const float* __restrict__ bias, float* __restrict__ C,
    int aSeg, int aOff, int aJoint, int cSeg, int cOff, int cJoint)
{
    __shared__ __align__(1024) __nv_bfloat16 As[2][BM * PAD];
    __shared__ __align__(1024) __nv_bfloat16 Bs[2][BN * PAD];

    const int tid = threadIdx.x;
    const int warp = tid >> 5, lane = tid & 31;
    const int wm = warp & 1, wn = warp >> 1;
    const int m0 = blockIdx.y * BM, n0 = blockIdx.x * BN;

    // ---- loader setup: 512 16B chunks per tile, thread -> chunks {tid, tid+256}
    const int r0 = tid >> 2, seg0 = tid & 3;           // chunk tid
    const int r1 = 64 + r0;                            // chunk tid+256 (same seg)
    const int mA0 = m0 + r0, mA1 = m0 + r1;
    const long ar0 = (long)(mA0 / aSeg) * aJoint + aOff + (mA0 % aSeg);
    const long ar1 = (long)(mA1 / aSeg) * aJoint + aOff + (mA1 % aSeg);
    const __nv_bfloat16* gA0 = A + ar0 * KBIG + seg0 * 8;
    const __nv_bfloat16* gA1 = A + ar1 * KBIG + seg0 * 8;
    const __nv_bfloat16* gB0 = Bw + (long)(n0 + r0) * KBIG + seg0 * 8;
    const __nv_bfloat16* gB1 = Bw + (long)(n0 + r1) * KBIG + seg0 * 8;
    const uint32_t sA0[2] = {smem_u32(&As[0][r0 * PAD + seg0 * 8]),
                             smem_u32(&As[1][r0 * PAD + seg0 * 8])};
    const uint32_t sA1[2] = {smem_u32(&As[0][r1 * PAD + seg0 * 8]),
                             smem_u32(&As[1][r1 * PAD + seg0 * 8])};
    const uint32_t sB0[2] = {smem_u32(&Bs[0][r0 * PAD + seg0 * 8]),
                             smem_u32(&Bs[1][r0 * PAD + seg0 * 8])};
    const uint32_t sB1[2] = {smem_u32(&Bs[0][r1 * PAD + seg0 * 8]),
                             smem_u32(&Bs[1][r1 * PAD + seg0 * 8])};

    // ---- ldmatrix address setup (element offsets; *2 for bytes)
    // A x4: row = base + (lane&15), koff = 8*(lane>>4)
    uint32_t laA[2][4];
#pragma unroll
    for (int mi = 0; mi < 4; mi++) {
        int row = wm * 64 + mi * 16 + (lane & 15);
        int koff = (lane >> 4) * 8;
#pragma unroll
        for (int st = 0; st < 2; st++)
            laA[st][mi] = smem_u32(&As[st][row * PAD + koff]);
    }
    // B x4 (two n8 tiles per ldmatrix): row = base + (lane&7) + ((lane>>4)<<3),
    // koff = ((lane>>3)&1)*8
    uint32_t laB[2][2];
#pragma unroll
    for (int p = 0; p < 2; p++) {
        int row = wn * 32 + p * 16 + (lane & 7) + ((lane >> 4) << 3);
        int koff = ((lane >> 3) & 1) * 8;
#pragma unroll
        for (int st = 0; st < 2; st++)
            laB[st][p] = smem_u32(&Bs[st][row * PAD + koff]);
    }

    float acc[4][4][4];
#pragma unroll
    for (int mi = 0; mi < 4; mi++)
#pragma unroll
        for (int ni = 0; ni < 4; ni++)
#pragma unroll
            for (int r = 0; r < 4; r++) acc[mi][ni][r] = 0.f;

    // ---- prologue: chunk 0 -> buf 0
    CP_ASYNC16(sA0[0], gA0);
    CP_ASYNC16(sA1[0], gA1);
    CP_ASYNC16(sB0[0], gB0);
    CP_ASYNC16(sB1[0], gB1);
    CP_COMMIT();

    for (int it = 0; it < NIT; it++) {
        if (it + 1 < NIT) {
            const int st = (it + 1) & 1;
            const long ko = (long)(it + 1) * BK;
            CP_ASYNC16(sA0[st], gA0 + ko);
            CP_ASYNC16(sA1[st], gA1 + ko);
            CP_ASYNC16(sB0[st], gB0 + ko);
            CP_ASYNC16(sB1[st], gB1 + ko);
            CP_COMMIT();
            CP_WAIT1();
        } else {
            CP_WAIT0();
        }
        __syncthreads();

        const int st = it & 1;
#pragma unroll
        for (int ks = 0; ks < 2; ks++) {
            const uint32_t kb = ks * 16 * 2;  // byte offset
            uint32_t a[4][4];
#pragma unroll
            for (int mi = 0; mi < 4; mi++)
                ldsm4(a[mi][0], a[mi][1], a[mi][2], a[mi][3], laA[st][mi] + kb);
            uint32_t b[4][2];
#pragma unroll
            for (int p = 0; p < 2; p++) {
                uint32_t q0, q1, q2, q3;
                ldsm4(q0, q1, q2, q3, laB[st][p] + kb);
                b[2 * p][0] = q0; b[2 * p][1] = q1;
                b[2 * p + 1][0] = q2; b[2 * p + 1][1] = q3;
            }
#pragma unroll
            for (int mi = 0; mi < 4; mi++)
#pragma unroll
                for (int ni = 0; ni < 4; ni++)
                    mma16816(acc[mi][ni], a[mi][0], a[mi][1], a[mi][2], a[mi][3],
                             b[ni][0], b[ni][1]);
        }
        __syncthreads();
    }

    // ---- epilogue: fp32 + bias, row-remapped
    const int lr = lane >> 2, lc = (lane & 3) * 2;
#pragma unroll
    for (int mi = 0; mi < 4; mi++) {
        const int mA = m0 + wm * 64 + mi * 16 + lr;
        const int mB = mA + 8;
        const long crA = (long)(mA / cSeg) * cJoint + cOff + (mA % cSeg);
        const long crB = (long)(mB / cSeg) * cJoint + cOff + (mB % cSeg);
        float* cpA = C + crA * DIM;
        float* cpB = C + crB * DIM;
#pragma unroll
        for (int ni = 0; ni < 4; ni++) {
            const int col = n0 + wn * 32 + ni * 8 + lc;
            const float b0v = bias[col], b1v = bias[col + 1];
            cpA[col]     = acc[mi][ni][0] + b0v;
            cpA[col + 1] = acc[mi][ni][1] + b1v;
            cpB[col]     = acc[mi][ni][2] + b0v;
            cpB[col + 1] = acc[mi][ni][3] + b1v;
        }
    }
}

// ---------------------------------------------------------------------------
// Fused per-head RMSNorm (+gain) + RoPE for Q and K.
// ---------------------------------------------------------------------------
__global__ __launch_bounds__(128) void rmsrope_k(
    float* __restrict__ Q, float* __restrict__ K,
    const float* __restrict__ cosb, const float* __restrict__ sinb,
    const float* __restrict__ gq, const float* __restrict__ gk,
    const float* __restrict__ gqc, const float* __restrict__ gkc)
{
    const int idx = blockIdx.x;
    const int h = idx % HEADS;
    const int s = (idx / HEADS) % SS;
    const int b = idx / (HEADS * SS);

    float* buf = (blockIdx.y == 0 ? Q : K) + ((long)(b * SS + s)) * DIM + h * HD;
    const float* g = (blockIdx.y == 0) ? (s < S_TXT ? gqc : gq)
                                       : (s < S_TXT ? gkc : gk);
    const int d = threadIdx.x;
    float v = buf[d];

    float sq = v * v;
#pragma unroll
    for (int off = 16; off; off >>= 1) sq += __shfl_xor_sync(0xffffffffu, sq, off);
    __shared__ float red[4];
    if ((d & 31) == 0) red[d >> 5] = sq;
    __syncthreads();
    const float tot = red[0] + red[1] + red[2] + red[3];
    const float inv = rsqrtf(tot * (1.0f / HD) + 1e-6f);

    __shared__ float sm[HD];
    sm[d] = v * inv * g[d];
    __syncthreads();

    const int i = d >> 1;
    const float c = cosb[s * (HD / 2) + i];
    const float sn = sinb[s * (HD / 2) + i];
    const float x1 = sm[2 * i];
    const float x2 = sm[2 * i + 1];
    buf[d] = (d & 1) ? (x1 * sn + x2 * c) : (x1 * c - x2 * sn);
}

// ---------------------------------------------------------------------------
// Flash attention, fp32 online softmax (as in R1).
// ---------------------------------------------------------------------------
__global__ __launch_bounds__(128) void attn_k(
    const float* __restrict__ Q, const float* __restrict__ K,
    const float* __restrict__ V, float* __restrict__ O)
{
    __shared__ float Qs[32][129];
    __shared__ float KVs[32][129];
    __shared__ float Ss[32][33];
    __shared__ float redm[4][32];
    __shared__ float redl[4][32];

    const int q0 = blockIdx.x * 32;
    const int bh = blockIdx.y;
    const int b = bh / HEADS;
    const int h = bh % HEADS;
    const long bofs = (long)b * SS * DIM + h * HD;

    const int t = threadIdx.x;
    const int r = t & 31;
    const int g = t >> 5;
    const int c0 = g * 8;
    const int d0 = g * 32;

    for (int idx = t; idx < 32 * HD; idx += 128) {
        const int rr = idx >> 7, d = idx & 127;
        Qs[rr][d] = Q[bofs + (long)(q0 + rr) * DIM + d] * SCALE_QK;
    }

    float m = -1e30f, l = 0.f;
    float o[32];
#pragma unroll
    for (int i = 0; i < 32; i++) o[i] = 0.f;
    __syncthreads();

    for (int kv0 = 0; kv0 < SS; kv0 += 32) {
        for (int idx = t; idx < 32 * HD; idx += 128) {
            const int rr = idx >> 7, d = idx & 127;
            KVs[rr][d] = K[bofs + (long)(kv0 + rr) * DIM + d];
        }
        __syncthreads();

        float sv[8];
#pragma unroll
        for (int j = 0; j < 8; j++) sv[j] = 0.f;
        for (int d = 0; d < HD; d++) {
            const float qv = Qs[r][d];
#pragma unroll
            for (int j = 0; j < 8; j++) sv[j] += qv * KVs[c0 + j][d];
        }
        float pmax = sv[0];
#pragma unroll
        for (int j = 1; j < 8; j++) pmax = fmaxf(pmax, sv[j]);
        redm[g][r] = pmax;
        __syncthreads();

        const float mch = fmaxf(fmaxf(redm[0][r], redm[1][r]),
                                fmaxf(redm[2][r], redm[3][r]));
        const float mnew = fmaxf(m, mch);
        const float alpha = __expf(m - mnew);
        float psum = 0.f;
#pragma unroll
        for (int j = 0; j < 8; j++) {
            const float p = __expf(sv[j] - mnew);
            Ss[r][c0 + j] = p;
            psum += p;
        }
        redl[g][r] = psum;

        for (int idx = t; idx < 32 * HD; idx += 128) {
            const int rr = idx >> 7, d = idx & 127;
            KVs[rr][d] = V[bofs + (long)(kv0 + rr) * DIM + d];
        }
        __syncthreads();

        l = l * alpha + redl[0][r] + redl[1][r] + redl[2][r] + redl[3][r];
        m = mnew;
#pragma unroll
        for (int i = 0; i < 32; i++) o[i] *= alpha;
        for (int c = 0; c < 32; c++) {
            const float p = Ss[r][c];
#pragma unroll
            for (int i = 0; i < 32; i++) o[i] += p * KVs[c][d0 + i];
        }
        __syncthreads();
    }

    const float invl = 1.0f / l;
    float* op = O + bofs + (long)(q0 + r) * DIM + d0;
#pragma unroll
    for (int i = 0; i < 32; i++) op[i] = o[i] * invl;
}

// ---------------------------------------------------------------------------
extern "C" void kernel_launch(void* const* d_in, const int* in_sizes, int n_in,
                              void* d_out, int out_size)
{
    const float* x    = (const float*)d_in[0];
    const float* ctx  = (const float*)d_in[1];
    const float* cosb = (const float*)d_in[2];
    const float* sinb = (const float*)d_in[3];
    const float* wq   = (const float*)d_in[4];
    const float* bq   = (const float*)d_in[5];
    const float* wk   = (const float*)d_in[6];
    const float* bk   = (const float*)d_in[7];
    const float* wv   = (const float*)d_in[8];
    const float* bv   = (const float*)d_in[9];
    const float* wqc  = (const float*)d_in[10];
    const float* bqc  = (const float*)d_in[11];
    const float* wkc  = (const float*)d_in[12];
    const float* bkc  = (const float*)d_in[13];
    const float* wvc  = (const float*)d_in[14];
    const float* bvc  = (const float*)d_in[15];
    const float* w_out     = (const float*)d_in[16];
    const float* b_out     = (const float*)d_in[17];
    const float* w_add_out = (const float*)d_in[18];
    const float* b_add_out = (const float*)d_in[19];
    const float* gq  = (const float*)d_in[20];
    const float* gk  = (const float*)d_in[21];
    const float* gqc = (const float*)d_in[22];
    const float* gkc = (const float*)d_in[23];

    float* out = (float*)d_out;

    float *Q, *K, *V, *AO;
    __nv_bfloat16 *Wt, *Ab;
    cudaGetSymbolAddress((void**)&Q, g_Qb);
    cudaGetSymbolAddress((void**)&K, g_Kb);
    cudaGetSymbolAddress((void**)&V, g_Vb);
    cudaGetSymbolAddress((void**)&AO, g_AO);
    cudaGetSymbolAddress((void**)&Wt, g_Wt);
    cudaGetSymbolAddress((void**)&Ab, g_Ab);

    const long WSL = (long)DIM * KBIG;
    const dim3 wgrid(DIM / 32, DIM / 32);
    const dim3 wblk(32, 8);
    // weight order: 0 wq, 1 wk, 2 wv, 3 wqc, 4 wkc, 5 wvc, 6 w_out, 7 w_add_out
    wsplit_k<<<wgrid, wblk>>>(wq,        Wt + 0 * WSL);
    wsplit_k<<<wgrid, wblk>>>(wk,        Wt + 1 * WSL);
    wsplit_k<<<wgrid, wblk>>>(wv,        Wt + 2 * WSL);
    wsplit_k<<<wgrid, wblk>>>(wqc,       Wt + 3 * WSL);
    wsplit_k<<<wgrid, wblk>>>(wkc,       Wt + 4 * WSL);
    wsplit_k<<<wgrid, wblk>>>(wvc,       Wt + 5 * WSL);
    wsplit_k<<<wgrid, wblk>>>(w_out,     Wt + 6 * WSL);
    wsplit_k<<<wgrid, wblk>>>(w_add_out, Wt + 7 * WSL);

    const dim3 gTxt(DIM / BN, (BB * S_TXT) / BM);   // (24, 8)
    const dim3 gImg(DIM / BN, (BB * S_IMG) / BM);   // (24, 16)

    // --- txt QKV: A = ctx (1024 rows) ---
    {
        int n = BB * S_TXT * DIM;
        asplit_k<<<(n + 255) / 256, 256>>>(ctx, Ab, n);
    }
    gemm_mma<<<gTxt, 256>>>(Ab, Wt + 3 * WSL, bqc, Q,
                            BB * S_TXT, 0, BB * S_TXT, S_TXT, 0, SS);
    gemm_mma<<<gTxt, 256>>>(Ab, Wt + 4 * WSL, bkc, K,
                            BB * S_TXT, 0, BB * S_TXT, S_TXT, 0, SS);
    gemm_mma<<<gTxt, 256>>>(Ab, Wt + 5 * WSL, bvc, V,
                            BB * S_TXT, 0, BB * S_TXT, S_TXT, 0, SS);

    // --- img QKV: A = x (2048 rows) ---
    {
        int n = BB * S_IMG * DIM;
        asplit_k<<<(n + 255) / 256, 256>>>(x, Ab, n);
    }
    gemm_mma<<<gImg, 256>>>(Ab, Wt + 0 * WSL, bq, Q,
                            BB * S_IMG, 0, BB * S_IMG, S_IMG, S_TXT, SS);
    gemm_mma<<<gImg, 256>>>(Ab, Wt + 1 * WSL, bk, K,
                            BB * S_IMG, 0, BB * S_IMG, S_IMG, S_TXT, SS);
    gemm_mma<<<gImg, 256>>>(Ab, Wt + 2 * WSL, bv, V,
                            BB * S_IMG, 0, BB * S_IMG, S_IMG, S_TXT, SS);

    // --- RMSNorm + RoPE ---
    rmsrope_k<<<dim3(BB * SS * HEADS, 2), 128>>>(Q, K, cosb, sinb, gq, gk, gqc, gkc);

    // --- attention ---
    attn_k<<<dim3(SS / 32, BB * HEADS), 128>>>(Q, K, V, AO);

    // --- split AO (joint 3072 rows) ---
    {
        int n = BB * SS * DIM;
        asplit_k<<<(n + 255) / 256, 256>>>(AO, Ab, n);
    }
    // --- output projections: d_out = [txt(2,512,3072) | img(2,1024,3072)] ---
    gemm_mma<<<gTxt, 256>>>(Ab, Wt + 7 * WSL, b_add_out, out,
                            S_TXT, 0, SS, BB * S_TXT, 0, BB * S_TXT);
    gemm_mma<<<gImg, 256>>>(Ab, Wt + 6 * WSL, b_out, out + (long)BB * S_TXT * DIM,
                            S_IMG, S_TXT, SS, BB * S_IMG, 0, BB * S_IMG);
}